// round 9
// baseline (speedup 1.0000x reference)
#include <cuda_runtime.h>

// PerturbedTopK: x (64,196) f32, noise (64,500,196) f32.
// out[b,k,d] = mean_n [ sorted(top49_idx(x_b + 0.05*noise_bn))[k] == d ].
//
// R9 structure: grid (2,64); each 512-thread block processes 250 rows of one
// batch, accumulating integer counts in a shared 49x196 histogram (ATOMS,
// no global atomics at all). Rows are walked sequentially per warp with
// software prefetch of the next row's loads. Warp 0 seeds the batch
// threshold from x while other warps zero the histogram. Per-row exact
// integer-key boundary-jump select (verified count==49; tie-skip/cap ->
// exact MSB radix fallback with index-order tie-break). Blocks flush to a
// static device scratch; a merge kernel writes out = (scr0+scr1)/500.

#define BATCH 64
#define NSAMP 500
#define DIM   196
#define TOPK  49
#define SIGMA 0.05f

#define HALF_ROWS (NSAMP / 2)          // 250
#define HISTN (TOPK * DIM)             // 9604
#define FULLM 0xffffffffu
#define NEGBIG (-3.402823466e38f)

__device__ int g_scr[2][BATCH][HISTN]; // static scratch (no allocation)

__device__ __forceinline__ unsigned f2key(float v) {
    unsigned u = __float_as_uint(v);
    return u ^ ((unsigned)((int)u >> 31) | 0x80000000u);
}
__device__ __forceinline__ float key2f(unsigned k) {
    unsigned u = (k & 0x80000000u) ? (k ^ 0x80000000u) : ~k;
    return __uint_as_float(u);
}
__device__ __forceinline__ unsigned fgt(float a, float b) {
    unsigned r;
    asm("set.gt.u32.f32 %0, %1, %2;" : "=r"(r) : "f"(a), "f"(b));
    return r;
}
__device__ __forceinline__ unsigned ugt(unsigned a, unsigned b) {
    unsigned r;
    asm("set.gt.u32.u32 %0, %1, %2;" : "=r"(r) : "r"(a), "r"(b));
    return r;
}

__global__ __launch_bounds__(512)
void ptopk_main(const float* __restrict__ x,
                const float* __restrict__ noise) {
    __shared__ __align__(16) int hist[HISTN];
    __shared__ unsigned sKseed;

    const int tid  = threadIdx.x;
    const int wid  = tid >> 5;
    const int lane = tid & 31;
    const int half = blockIdx.x;
    const int b    = blockIdx.y;
    const unsigned lt = (1u << lane) - 1u;

    // Zero histogram (all warps participate; warp 0 also seeds below).
    for (int i = tid; i < HISTN; i += 512) hist[i] = 0;

    // x row resident in registers for the whole block lifetime.
    float xv[7];
    #pragma unroll
    for (int j = 0; j < 7; j++) {
        const int d = j * 32 + lane;
        xv[j] = (d < DIM) ? x[b * DIM + d] : NEGBIG;
    }

    // Warp 0: per-batch seed threshold from x alone (hint only; any value safe).
    if (wid == 0) {
        float piv = 0.674f;
        #pragma unroll 1
        for (int it = 0; it < 40; ++it) {
            unsigned a = 0;
            #pragma unroll
            for (int j = 0; j < 7; j++) a += fgt(xv[j], piv);
            const int c = -(int)__reduce_add_sync(FULLM, (int)a);
            if (c == TOPK) break;
            if (c > TOPK) {
                unsigned mk = 0xFFFFFFFFu;
                #pragma unroll
                for (int j = 0; j < 7; j++)
                    mk = min(mk, (xv[j] > piv) ? f2key(xv[j]) : 0xFFFFFFFFu);
                piv = key2f(__reduce_min_sync(FULLM, mk));
            } else {
                unsigned Mk = 0u;
                #pragma unroll
                for (int j = 0; j < 7; j++)
                    Mk = max(Mk, (xv[j] > piv) ? 0u : f2key(xv[j]));
                piv = key2f(__reduce_max_sync(FULLM, Mk) - 1u);
            }
        }
        if (lane == 0) sKseed = f2key(piv);
    }
    __syncthreads();
    const unsigned Kseed = sKseed;

    const size_t rowbase = (size_t)b * NSAMP + (size_t)half * HALF_ROWS;

    // Preload first row for this warp.
    int r = wid;
    float nv[7];
    {
        const float* nr = noise + (rowbase + r) * DIM;
        #pragma unroll
        for (int j = 0; j < 7; j++) {
            const int d = j * 32 + lane;
            nv[j] = (d < DIM) ? nr[d] : 0.0f;
        }
    }

    #pragma unroll 1
    while (r < HALF_ROWS) {
        const int rn = r + 16;
        float pv[7];
        if (rn < HALF_ROWS) {                     // prefetch next row
            const float* nr2 = noise + (rowbase + rn) * DIM;
            #pragma unroll
            for (int j = 0; j < 7; j++) {
                const int d = j * 32 + lane;
                pv[j] = (d < DIM) ? nr2[d] : 0.0f;
            }
        }

        // Monotonic integer keys; padding -> 0 (below any real key).
        unsigned key[7];
        #pragma unroll
        for (int j = 0; j < 7; j++) {
            const int d = j * 32 + lane;
            key[j] = (d < DIM) ? f2key(fmaf(nv[j], SIGMA, xv[j])) : 0u;
        }

        // ---- exact boundary-jump select in key domain ----
        unsigned Kthr = Kseed;
        unsigned a = 0;
        #pragma unroll
        for (int j = 0; j < 7; j++) a += ugt(key[j], Kthr);
        int c = -(int)__reduce_add_sync(FULLM, (int)a);

        #pragma unroll 1
        for (int it = 0; it < 12 && c != TOPK; ++it) {
            if (c > TOPK) {
                unsigned mk = 0xFFFFFFFFu;        // min selected key
                #pragma unroll
                for (int j = 0; j < 7; j++)
                    mk = min(mk, (key[j] > Kthr) ? key[j] : 0xFFFFFFFFu);
                Kthr = __reduce_min_sync(FULLM, mk);
            } else {
                unsigned Mk = 0u;                 // max unselected key
                #pragma unroll
                for (int j = 0; j < 7; j++)
                    Mk = max(Mk, (key[j] > Kthr) ? 0u : key[j]);
                Kthr = __reduce_max_sync(FULLM, Mk) - 1u;
            }
            unsigned a2 = 0;
            #pragma unroll
            for (int j = 0; j < 7; j++) a2 += ugt(key[j], Kthr);
            c = -(int)__reduce_add_sync(FULLM, (int)a2);
        }

        if (c == TOPK) {
            // Tie-free: rank by ascending index, accumulate in smem.
            int base = 0;
            #pragma unroll
            for (int j = 0; j < 7; j++) {
                const int d = j * 32 + lane;
                const bool s = key[j] > Kthr;
                const unsigned mb = __ballot_sync(FULLM, s);
                if (s) {
                    const int rank = base + __popc(mb & lt);
                    atomicAdd(&hist[rank * DIM + d], 1);
                }
                base += __popc(mb);
            }
        } else {
            // ---- exact MSB radix fallback with index-order tie-break ----
            unsigned actm = (6 * 32 + lane < DIM) ? 0x7Fu : 0x3Fu;
            int k = TOPK, matching = DIM, s = 0;
            unsigned P = 0u;
            #pragma unroll 1
            for (int bit = 31; bit >= 0; --bit) {
                const unsigned m = 1u << bit;
                int cc = 0;
                #pragma unroll
                for (int j = 0; j < 7; j++)
                    cc += (((actm >> j) & 1u) && (key[j] & m)) ? 1 : 0;
                cc = __reduce_add_sync(FULLM, cc);
                if (cc >= k) {
                    P |= m; matching = cc;
                    #pragma unroll
                    for (int j = 0; j < 7; j++)
                        if (!(key[j] & m)) actm &= ~(1u << j);
                } else {
                    k -= cc; matching -= cc;
                    #pragma unroll
                    for (int j = 0; j < 7; j++)
                        if (key[j] & m) actm &= ~(1u << j);
                }
                s = bit;
                if (matching == k) break;
            }
            const unsigned Ph = P >> s;
            int gtb = 0, eqb = 0;
            #pragma unroll
            for (int j = 0; j < 7; j++) {
                const int d = j * 32 + lane;
                const bool gt = (d < DIM) && ((key[j] >> s) > Ph);
                const bool eq = ((actm >> j) & 1u) != 0u;
                const unsigned mg = __ballot_sync(FULLM, gt);
                const unsigned me = __ballot_sync(FULLM, eq);
                const int gtp = gtb + __popc(mg & lt);
                const int eqp = eqb + __popc(me & lt);
                if (gt || (eq && eqp < k)) {
                    const int rank = gtp + min(eqp, k);
                    atomicAdd(&hist[rank * DIM + d], 1);
                }
                gtb += __popc(mg);
                eqb += __popc(me);
            }
        }

        r = rn;
        #pragma unroll
        for (int j = 0; j < 7; j++) nv[j] = pv[j];
    }

    // Flush histogram to scratch (plain vectorized stores).
    __syncthreads();
    const int4* src = (const int4*)hist;
    int4* dst = (int4*)g_scr[half][b];
    for (int i = tid; i < HISTN / 4; i += 512) dst[i] = src[i];
}

__global__ __launch_bounds__(256)
void merge_kernel(float* __restrict__ out) {
    const int b   = blockIdx.y;
    const int off = blockIdx.x * 256 + threadIdx.x;
    if (off >= HISTN / 4) return;
    const float invn = 1.0f / (float)NSAMP;
    const int4 a = ((const int4*)g_scr[0][b])[off];
    const int4 c = ((const int4*)g_scr[1][b])[off];
    float4 o;
    o.x = (float)(a.x + c.x) * invn;
    o.y = (float)(a.y + c.y) * invn;
    o.z = (float)(a.z + c.z) * invn;
    o.w = (float)(a.w + c.w) * invn;
    ((float4*)out)[b * (HISTN / 4) + off] = o;
}

extern "C" void kernel_launch(void* const* d_in, const int* in_sizes, int n_in,
                              void* d_out, int out_size) {
    const float* x     = (const float*)d_in[0];
    const float* noise = (const float*)d_in[1];
    if (n_in >= 2 && in_sizes[0] > in_sizes[1]) {
        x     = (const float*)d_in[1];
        noise = (const float*)d_in[0];
    }
    float* out = (float*)d_out;

    dim3 mg(2, BATCH, 1);                       // 128 blocks, 512 threads
    ptopk_main<<<mg, 512>>>(x, noise);
    dim3 gg((HISTN / 4 + 255) / 256, BATCH, 1); // merge + scale
    merge_kernel<<<gg, 256>>>(out);
}

// round 10
// speedup vs baseline: 1.0843x; 1.0843x over previous
#include <cuda_runtime.h>

// PerturbedTopK: x (64,196) f32, noise (64,500,196) f32.
// out[b,k,d] = mean_n [ sorted(top49_idx(x_b + 0.05*noise_bn))[k] == d ].
//
// R10: grid (10,64) x 256 threads; each block does 50 rows of one batch into
// a u16-packed shared histogram (9.6KB; counts<=50/block so halves can't
// carry). 640 blocks all co-resident (single wave) -> latency overlap that
// R9 lacked. Per-warp sequential rows with software prefetch. Exact
// integer-key boundary-jump select seeded from the batch threshold of x
// (verified count==49; cap/tie -> exact MSB radix fallback, index-order
// tie-break). Blocks flush packed words to static scratch; merge sums 10
// packed words per cell-pair (no carry: totals<=500) and writes out/500.

#define BATCH 64
#define NSAMP 500
#define DIM   196
#define TOPK  49
#define SIGMA 0.05f

#define COPIES 10
#define ROWS_PB (NSAMP / COPIES)   // 50
#define HISTN (TOPK * DIM)         // 9604 cells
#define HISTW (HISTN / 2)          // 4802 packed words
#define FULLM 0xffffffffu
#define NEGBIG (-3.402823466e38f)

__device__ unsigned g_scr[COPIES][BATCH][HISTW];  // static scratch

__device__ __forceinline__ unsigned f2key(float v) {
    unsigned u = __float_as_uint(v);
    return u ^ ((unsigned)((int)u >> 31) | 0x80000000u);
}
__device__ __forceinline__ float key2f(unsigned k) {
    unsigned u = (k & 0x80000000u) ? (k ^ 0x80000000u) : ~k;
    return __uint_as_float(u);
}
__device__ __forceinline__ unsigned fgt(float a, float b) {
    unsigned r;
    asm("set.gt.u32.f32 %0, %1, %2;" : "=r"(r) : "f"(a), "f"(b));
    return r;
}
__device__ __forceinline__ unsigned ugt(unsigned a, unsigned b) {
    unsigned r;
    asm("set.gt.u32.u32 %0, %1, %2;" : "=r"(r) : "r"(a), "r"(b));
    return r;
}

__global__ __launch_bounds__(256)
void ptopk_main(const float* __restrict__ x,
                const float* __restrict__ noise) {
    __shared__ __align__(16) unsigned hist[HISTW];
    __shared__ unsigned sKseed;

    const int tid  = threadIdx.x;
    const int wid  = tid >> 5;
    const int lane = tid & 31;
    const int copy = blockIdx.x;
    const int b    = blockIdx.y;
    const unsigned lt  = (1u << lane) - 1u;
    const unsigned inc = 1u << ((lane & 1) << 4);   // which u16 half (d&1==lane&1)

    for (int i = tid; i < HISTW; i += 256) hist[i] = 0;

    // x row resident in registers.
    float xv[7];
    #pragma unroll
    for (int j = 0; j < 7; j++) {
        const int d = j * 32 + lane;
        xv[j] = (d < DIM) ? x[b * DIM + d] : NEGBIG;
    }

    // Warp 0: batch seed threshold from x alone (hint only; any value safe).
    if (wid == 0) {
        float piv = 0.674f;
        #pragma unroll 1
        for (int it = 0; it < 40; ++it) {
            unsigned a = 0;
            #pragma unroll
            for (int j = 0; j < 7; j++) a += fgt(xv[j], piv);
            const int c = -(int)__reduce_add_sync(FULLM, (int)a);
            if (c == TOPK) break;
            if (c > TOPK) {
                unsigned mk = 0xFFFFFFFFu;
                #pragma unroll
                for (int j = 0; j < 7; j++)
                    mk = min(mk, (xv[j] > piv) ? f2key(xv[j]) : 0xFFFFFFFFu);
                piv = key2f(__reduce_min_sync(FULLM, mk));
            } else {
                unsigned Mk = 0u;
                #pragma unroll
                for (int j = 0; j < 7; j++)
                    Mk = max(Mk, (xv[j] > piv) ? 0u : f2key(xv[j]));
                piv = key2f(__reduce_max_sync(FULLM, Mk) - 1u);
            }
        }
        if (lane == 0) sKseed = f2key(piv);
    }
    __syncthreads();
    const unsigned Kseed = sKseed;

    const size_t rowbase = (size_t)b * NSAMP + (size_t)copy * ROWS_PB;

    // Preload first row for this warp (wid < 8 <= ROWS_PB always valid).
    int r = wid;
    float nv[7];
    {
        const float* nr = noise + (rowbase + r) * DIM;
        #pragma unroll
        for (int j = 0; j < 7; j++) {
            const int d = j * 32 + lane;
            nv[j] = (d < DIM) ? nr[d] : 0.0f;
        }
    }

    #pragma unroll 1
    while (r < ROWS_PB) {
        const int rn = r + 8;
        float pv[7];
        if (rn < ROWS_PB) {                       // prefetch next row
            const float* nr2 = noise + (rowbase + rn) * DIM;
            #pragma unroll
            for (int j = 0; j < 7; j++) {
                const int d = j * 32 + lane;
                pv[j] = (d < DIM) ? nr2[d] : 0.0f;
            }
        }

        // Monotonic integer keys; padding -> 0 (below any real key).
        unsigned key[7];
        #pragma unroll
        for (int j = 0; j < 7; j++) {
            const int d = j * 32 + lane;
            key[j] = (d < DIM) ? f2key(fmaf(nv[j], SIGMA, xv[j])) : 0u;
        }

        // ---- exact boundary-jump select in key domain ----
        unsigned Kthr = Kseed;
        unsigned a = 0;
        #pragma unroll
        for (int j = 0; j < 7; j++) a += ugt(key[j], Kthr);
        int c = -(int)__reduce_add_sync(FULLM, (int)a);

        #pragma unroll 1
        for (int it = 0; it < 12 && c != TOPK; ++it) {
            if (c > TOPK) {
                unsigned mk = 0xFFFFFFFFu;        // min selected key
                #pragma unroll
                for (int j = 0; j < 7; j++)
                    mk = min(mk, (key[j] > Kthr) ? key[j] : 0xFFFFFFFFu);
                Kthr = __reduce_min_sync(FULLM, mk);
            } else {
                unsigned Mk = 0u;                 // max unselected key
                #pragma unroll
                for (int j = 0; j < 7; j++)
                    Mk = max(Mk, (key[j] > Kthr) ? 0u : key[j]);
                Kthr = __reduce_max_sync(FULLM, Mk) - 1u;
            }
            unsigned a2 = 0;
            #pragma unroll
            for (int j = 0; j < 7; j++) a2 += ugt(key[j], Kthr);
            c = -(int)__reduce_add_sync(FULLM, (int)a2);
        }

        if (c == TOPK) {
            // Tie-free: rank by ascending index; packed u16 smem atomic.
            int base = 0;
            #pragma unroll
            for (int j = 0; j < 7; j++) {
                const int d = j * 32 + lane;
                const bool s = key[j] > Kthr;
                const unsigned mb = __ballot_sync(FULLM, s);
                if (s) {
                    const int rank = base + __popc(mb & lt);
                    atomicAdd(&hist[(rank * DIM + d) >> 1], inc);
                }
                base += __popc(mb);
            }
        } else {
            // ---- exact MSB radix fallback with index-order tie-break ----
            unsigned actm = (6 * 32 + lane < DIM) ? 0x7Fu : 0x3Fu;
            int k = TOPK, matching = DIM, s = 0;
            unsigned P = 0u;
            #pragma unroll 1
            for (int bit = 31; bit >= 0; --bit) {
                const unsigned m = 1u << bit;
                int cc = 0;
                #pragma unroll
                for (int j = 0; j < 7; j++)
                    cc += (((actm >> j) & 1u) && (key[j] & m)) ? 1 : 0;
                cc = __reduce_add_sync(FULLM, cc);
                if (cc >= k) {
                    P |= m; matching = cc;
                    #pragma unroll
                    for (int j = 0; j < 7; j++)
                        if (!(key[j] & m)) actm &= ~(1u << j);
                } else {
                    k -= cc; matching -= cc;
                    #pragma unroll
                    for (int j = 0; j < 7; j++)
                        if (key[j] & m) actm &= ~(1u << j);
                }
                s = bit;
                if (matching == k) break;
            }
            const unsigned Ph = P >> s;
            int gtb = 0, eqb = 0;
            #pragma unroll
            for (int j = 0; j < 7; j++) {
                const int d = j * 32 + lane;
                const bool gt = (d < DIM) && ((key[j] >> s) > Ph);
                const bool eq = ((actm >> j) & 1u) != 0u;
                const unsigned mg = __ballot_sync(FULLM, gt);
                const unsigned me = __ballot_sync(FULLM, eq);
                const int gtp = gtb + __popc(mg & lt);
                const int eqp = eqb + __popc(me & lt);
                if (gt || (eq && eqp < k)) {
                    const int rank = gtp + min(eqp, k);
                    atomicAdd(&hist[(rank * DIM + d) >> 1], inc);
                }
                gtb += __popc(mg);
                eqb += __popc(me);
            }
        }

        r = rn;
        #pragma unroll
        for (int j = 0; j < 7; j++) nv[j] = pv[j];
    }

    // Flush packed histogram to scratch (vectorized, coalesced).
    __syncthreads();
    const uint2* src = (const uint2*)hist;
    uint2* dst = (uint2*)g_scr[copy][b];
    for (int i = tid; i < HISTW / 2; i += 256) dst[i] = src[i];
}

__global__ __launch_bounds__(256)
void merge_kernel(float* __restrict__ out) {
    const int b   = blockIdx.y;
    const int off = blockIdx.x * 256 + threadIdx.x;
    if (off >= HISTW) return;
    unsigned s = 0;
    #pragma unroll
    for (int c = 0; c < COPIES; c++) s += g_scr[c][b][off];  // halves <= 500: no carry
    const float invn = 1.0f / (float)NSAMP;
    float2 o;
    o.x = (float)(s & 0xFFFFu) * invn;
    o.y = (float)(s >> 16) * invn;
    ((float2*)out)[(size_t)b * HISTW + off] = o;
}

extern "C" void kernel_launch(void* const* d_in, const int* in_sizes, int n_in,
                              void* d_out, int out_size) {
    const float* x     = (const float*)d_in[0];
    const float* noise = (const float*)d_in[1];
    if (n_in >= 2 && in_sizes[0] > in_sizes[1]) {
        x     = (const float*)d_in[1];
        noise = (const float*)d_in[0];
    }
    float* out = (float*)d_out;

    dim3 mg(COPIES, BATCH, 1);                 // 640 blocks x 256 threads
    ptopk_main<<<mg, 256>>>(x, noise);
    dim3 gg((HISTW + 255) / 256, BATCH, 1);    // 19 x 64 merge blocks
    merge_kernel<<<gg, 256>>>(out);
}